// round 9
// baseline (speedup 1.0000x reference)
#include <cuda_runtime.h>

#define NN    4
#define CC    20
#define HH    64
#define WWID  2048
#define KHW   5
#define PLANE (HH * WWID)     // 131072

#define TPB   128
#define TILE  256             // output px per block, 2 px/thread

__global__ __launch_bounds__(TPB, 5)
void lcxyz_kernel(const float* __restrict__ xyz,
                  const float* __restrict__ softmax,
                  const void* __restrict__ mask,
                  float* __restrict__ out)
{
    __shared__ int sh_mode;

    const int t  = threadIdx.x;
    const int w0 = blockIdx.x * TILE;
    const int h  = blockIdx.y;
    const int n  = blockIdx.z;

    // ---- mask dtype detection (warp 0): 0=u8, 1=i32, 2=f32 ----
    if (t < 32) {
        const unsigned* m = (const unsigned*)mask;
        unsigned w1 = m[t], w2 = m[t + 32];
        bool i32ok = (w1 <= 1u) && (w2 <= 1u);
        bool f32ok = (w1 == 0u || w1 == 0x3F800000u) &&
                     (w2 == 0u || w2 == 0x3F800000u);
        unsigned bi = __ballot_sync(0xFFFFFFFFu, i32ok);
        unsigned bf = __ballot_sync(0xFFFFFFFFu, f32ok);
        if (t == 0) sh_mode = (bi == 0xFFFFFFFFu) ? 1 : ((bf == 0xFFFFFFFFu) ? 2 : 0);
    }

    int hrow[KHW];
#pragma unroll
    for (int r = 0; r < KHW; ++r)
        hrow[r] = min(max(h + r - 2, 0), HH - 1);

    __syncthreads();            // sh_mode visible (only barrier in the kernel)
    const int mmode = sh_mode;

    // ---- Phase 1: masked Gaussian weights for 2 adjacent pixels ----
    const int wa = w0 + 2 * t;  // pixel 0; pixel 1 = wa+1

    const float* Xx = xyz + (size_t)n * 3 * PLANE;
    const float* Xy = Xx + PLANE;
    const float* Xz = Xy + PLANE;
    const size_t mbase = (size_t)n * PLANE;
    const unsigned char* mk_u8  = (const unsigned char*)mask + mbase;
    const int*           mk_i32 = (const int*)mask + mbase;
    const float*         mk_f32 = (const float*)mask + mbase;

    const float cx0 = Xx[h * WWID + wa],     cy0 = Xy[h * WWID + wa],     cz0 = Xz[h * WWID + wa];
    const float cx1 = Xx[h * WWID + wa + 1], cy1 = Xy[h * WWID + wa + 1], cz1 = Xz[h * WWID + wa + 1];

    float gm0[25], gm1[25];
#pragma unroll
    for (int dy = 0; dy < KHW; ++dy) {
        const int hc  = hrow[dy];
        const int hh  = h + dy - 2;
        const bool hok = (hh >= 0) && (hh < HH);
        float m[6], nx[6], ny[6], nz[6];
#pragma unroll
        for (int j = 0; j < 6; ++j) {
            int wraw = wa + j - 2;
            int ww = min(max(wraw, 0), WWID - 1);
            int idx = hc * WWID + ww;
            nx[j] = Xx[idx];  ny[j] = Xy[idx];  nz[j] = Xz[idx];
            bool ok = hok && (wraw >= 0) && (wraw < WWID);
            float mv = 0.0f;
            if (ok) {
                if (mmode == 1)      mv = (float)mk_i32[idx];
                else if (mmode == 2) mv = mk_f32[idx];
                else                 mv = (float)mk_u8[idx];
            }
            m[j] = mv;
        }
#pragma unroll
        for (int dx = 0; dx < KHW; ++dx) {
            float ax = nx[dx] - cx0, ay = ny[dx] - cy0, az = nz[dx] - cz0;
            float d2a = fmaf(ax, ax, fmaf(ay, ay, az * az));
            gm0[dy*5+dx] = m[dx] * __expf(-0.5f * d2a);
            float bx = nx[dx+1] - cx1, by = ny[dx+1] - cy1, bz = nz[dx+1] - cz1;
            float d2b = fmaf(bx, bx, fmaf(by, by, bz * bz));
            gm1[dy*5+dx] = m[dx+1] * __expf(-0.5f * d2b);
        }
    }

    // ---- Phase 2: stream softmax straight from gmem (L1/L2), no staging ----
    // Clamped window-start columns. Displaced values only multiply gm==0 taps.
    const int c0 = max(wa - 2, 0);            // left pair  (cols wa-2, wa-1)
    const int c1 = wa;                        // mid pair   (cols wa,   wa+1) — always in range
    const int c2 = min(wa + 2, WWID - 2);     // right pair (cols wa+2, wa+3)

    int roff[KHW];
#pragma unroll
    for (int r = 0; r < KHW; ++r)
        roff[r] = hrow[r] * WWID;

    const float* sm_base = softmax + (size_t)(n * CC) * PLANE;
    float* outp = out + ((size_t)(n * CC) * HH + h) * WWID + wa;

#pragma unroll 2
    for (int ch = 0; ch < CC; ++ch) {
        const float* cb = sm_base + (size_t)ch * PLANE;

        float a0e = 0.0f, a0o = 0.0f, a1e = 0.0f, a1o = 0.0f;
#pragma unroll
        for (int dy = 0; dy < KHW; ++dy) {
            const float* rp = cb + roff[dy];
            float2 s01 = *(const float2*)(rp + c0);
            float2 s23 = *(const float2*)(rp + c1);
            float2 s45 = *(const float2*)(rp + c2);
            float s0 = s01.x, s1 = s01.y, s2 = s23.x,
                  s3 = s23.y, s4 = s45.x, s5 = s45.y;
            a0e = fmaf(gm0[dy*5+0], s0, a0e);  a1e = fmaf(gm1[dy*5+0], s1, a1e);
            a0o = fmaf(gm0[dy*5+1], s1, a0o);  a1o = fmaf(gm1[dy*5+1], s2, a1o);
            a0e = fmaf(gm0[dy*5+2], s2, a0e);  a1e = fmaf(gm1[dy*5+2], s3, a1e);
            a0o = fmaf(gm0[dy*5+3], s3, a0o);  a1o = fmaf(gm1[dy*5+3], s4, a1o);
            a0e = fmaf(gm0[dy*5+4], s4, a0e);  a1e = fmaf(gm1[dy*5+4], s5, a1e);
        }
        *(float2*)(outp + (size_t)ch * PLANE) = make_float2(a0e + a0o, a1e + a1o);
    }
}

extern "C" void kernel_launch(void* const* d_in, const int* in_sizes, int n_in,
                              void* d_out, int out_size)
{
    const float* xyz     = (const float*)d_in[0];
    const float* softmax = (const float*)d_in[1];
    const void*  mask    = d_in[2];
    float*       out     = (float*)d_out;

    dim3 grid(WWID / TILE, HH, NN);   // (8, 64, 4) = 2048 blocks
    dim3 block(TPB);
    lcxyz_kernel<<<grid, block>>>(xyz, softmax, mask, out);
}

// round 10
// speedup vs baseline: 1.5381x; 1.5381x over previous
#include <cuda_runtime.h>

#define NN    4
#define CC    20
#define HH    64
#define WWID  2048
#define KHW   5
#define PLANE (HH * WWID)       // 131072

#define TPB    128
#define TILE   256              // block tile; 64 px per warp, 2 px per lane
#define WCOLS  72               // warp-staged cols: wstart-4 .. wstart+67
#define NROWV4 (WCOLS / 4)      // 18 float4 per row
#define CHG    2                // channels per group
#define NGROUPS (CC / CHG)      // 10
#define STG_FLTS (CHG * KHW * WCOLS)   // 720 floats per warp stage
#define NSTAGE 3
#define WSLOTS (CHG * KHW * NROWV4)    // 180 float4 copies per warp group
#define SL_PT  5                        // 5 full slots per lane (160), +1 for lane<20
#define SL_REM (WSLOTS - 32 * SL_PT)    // 20

__device__ __forceinline__ void cp_async16(void* smem, const void* gmem)
{
    unsigned saddr = (unsigned)__cvta_generic_to_shared(smem);
    asm volatile("cp.async.cg.shared.global [%0], [%1], 16;\n"
                 :: "r"(saddr), "l"(gmem));
}
__device__ __forceinline__ void cp_commit()
{
    asm volatile("cp.async.commit_group;\n" ::: "memory");
}
template <int N>
__device__ __forceinline__ void cp_wait()
{
    asm volatile("cp.async.wait_group %0;\n" :: "n"(N) : "memory");
}

__global__ __launch_bounds__(TPB, 5)
void lcxyz_kernel(const float* __restrict__ xyz,
                  const float* __restrict__ softmax,
                  const void* __restrict__ mask,
                  float* __restrict__ out)
{
    __shared__ float ring[4][NSTAGE][STG_FLTS];   // warp-private rings (34560 B)

    const int t    = threadIdx.x;
    const int wrp  = t >> 5;
    const int lane = t & 31;
    const int w0   = blockIdx.x * TILE;
    const int h    = blockIdx.y;
    const int n    = blockIdx.z;

    // ---- mask dtype detection, per-warp (ballot result is warp-uniform) ----
    int mmode;
    {
        const unsigned* m = (const unsigned*)mask;
        unsigned v1 = m[lane], v2 = m[lane + 32];
        bool i32ok = (v1 <= 1u) && (v2 <= 1u);
        bool f32ok = (v1 == 0u || v1 == 0x3F800000u) &&
                     (v2 == 0u || v2 == 0x3F800000u);
        unsigned bi = __ballot_sync(0xFFFFFFFFu, i32ok);
        unsigned bf = __ballot_sync(0xFFFFFFFFu, f32ok);
        mmode = (bi == 0xFFFFFFFFu) ? 1 : ((bf == 0xFFFFFFFFu) ? 2 : 0);
    }

    int hrow[KHW];
#pragma unroll
    for (int r = 0; r < KHW; ++r)
        hrow[r] = min(max(h + r - 2, 0), HH - 1);

    const int wstart = w0 + 64 * wrp;       // warp's first output pixel
    const int wa     = wstart + 2 * lane;   // lane's pixel 0; pixel 1 = wa+1

    const float* sm_base = softmax + (size_t)(n * CC) * PLANE;
    float* wring = &ring[wrp][0][0];

    // ---- Precompute warp staging slots: 5 per lane + 1 extra for lane<20 ----
    unsigned soff[SL_PT], goff[SL_PT];
    unsigned soffX = 0, goffX = 0;
    const bool hasX = (lane < SL_REM);
#pragma unroll
    for (int k = 0; k <= SL_PT; ++k) {
        int j = (k < SL_PT) ? (lane + 32 * k) : (32 * SL_PT + lane);
        int ch  = j / (KHW * NROWV4);
        int rem = j - ch * (KHW * NROWV4);
        int rr  = rem / NROWV4;
        int i   = rem - rr * NROWV4;
        unsigned so = ch * (KHW * WCOLS) + rr * WCOLS + 4 * i;
        int gcol = wstart - 4 + 4 * i;
        gcol = min(max(gcol, 0), WWID - 4);       // edge garbage killed by gm=0
        unsigned go = ch * PLANE + hrow[rr] * WWID + gcol;
        if (k < SL_PT) { soff[k] = so; goff[k] = go; }
        else           { soffX   = so; goffX   = go; }
    }

    // ---- Prologue: prefetch groups 0 (stage 0) and 1 (stage 1) ----
#pragma unroll
    for (int k = 0; k < SL_PT; ++k)
        cp_async16(wring + soff[k], sm_base + goff[k]);
    if (hasX) cp_async16(wring + soffX, sm_base + goffX);
    cp_commit();
#pragma unroll
    for (int k = 0; k < SL_PT; ++k)
        cp_async16(wring + STG_FLTS + soff[k], sm_base + CHG * PLANE + goff[k]);
    if (hasX) cp_async16(wring + STG_FLTS + soffX, sm_base + CHG * PLANE + goffX);
    cp_commit();

    // ---- Phase 1: masked Gaussian weights for 2 adjacent pixels (direct gmem) ----
    const float* Xx = xyz + (size_t)n * 3 * PLANE;
    const float* Xy = Xx + PLANE;
    const float* Xz = Xy + PLANE;
    const size_t mbase = (size_t)n * PLANE;
    const unsigned char* mk_u8  = (const unsigned char*)mask + mbase;
    const int*           mk_i32 = (const int*)mask + mbase;
    const float*         mk_f32 = (const float*)mask + mbase;

    const float cx0 = Xx[h * WWID + wa],     cy0 = Xy[h * WWID + wa],     cz0 = Xz[h * WWID + wa];
    const float cx1 = Xx[h * WWID + wa + 1], cy1 = Xy[h * WWID + wa + 1], cz1 = Xz[h * WWID + wa + 1];

    float gm0[25], gm1[25];
#pragma unroll
    for (int dy = 0; dy < KHW; ++dy) {
        const int hc  = hrow[dy];
        const int hh  = h + dy - 2;
        const bool hok = (hh >= 0) && (hh < HH);
        float m[6], nx[6], ny[6], nz[6];
#pragma unroll
        for (int j = 0; j < 6; ++j) {
            int wraw = wa + j - 2;
            int ww = min(max(wraw, 0), WWID - 1);
            int idx = hc * WWID + ww;
            nx[j] = Xx[idx];  ny[j] = Xy[idx];  nz[j] = Xz[idx];
            bool ok = hok && (wraw >= 0) && (wraw < WWID);
            float mv = 0.0f;
            if (ok) {
                if (mmode == 1)      mv = (float)mk_i32[idx];
                else if (mmode == 2) mv = mk_f32[idx];
                else                 mv = (float)mk_u8[idx];
            }
            m[j] = mv;
        }
#pragma unroll
        for (int dx = 0; dx < KHW; ++dx) {
            float ax = nx[dx] - cx0, ay = ny[dx] - cy0, az = nz[dx] - cz0;
            float d2a = fmaf(ax, ax, fmaf(ay, ay, az * az));
            gm0[dy*5+dx] = m[dx] * __expf(-0.5f * d2a);
            float bx = nx[dx+1] - cx1, by = ny[dx+1] - cy1, bz = nz[dx+1] - cz1;
            float d2b = fmaf(bx, bx, fmaf(by, by, bz * bz));
            gm1[dy*5+dx] = m[dx+1] * __expf(-0.5f * d2b);
        }
    }

    // ---- Phase 2: warp-autonomous 3-stage ring, prefetch distance 2 ----
    // Lane's window in staged coords: wa-2 -> col 2*lane+2 (8B aligned).
    const int cbase = 2 * lane + 2;
    float* outp = out + ((size_t)(n * CC) * HH + h) * WWID + wa;

    int s_rd = 0, s_wr = 2;
    for (int g = 0; g < NGROUPS; ++g) {
        if (g < NGROUPS - 1) cp_wait<1>();    // group g landed (g+1 may be in flight)
        else                 cp_wait<0>();
        __syncwarp();                          // cross-lane visibility; orders ring reuse

        if (g + 2 < NGROUPS) {                // prefetch into s_wr (= stage read at g-1)
            const float* gb = sm_base + (size_t)(g + 2) * (CHG * PLANE);
            float* buf = wring + s_wr * STG_FLTS;
#pragma unroll
            for (int k = 0; k < SL_PT; ++k)
                cp_async16(buf + soff[k], gb + goff[k]);
            if (hasX) cp_async16(buf + soffX, gb + goffX);
            cp_commit();
        }

        const float* B = wring + s_rd * STG_FLTS;
#pragma unroll
        for (int ch = 0; ch < CHG; ++ch) {
            const float* Bc = B + ch * (KHW * WCOLS);
            float a0e = 0.0f, a0o = 0.0f, a1e = 0.0f, a1o = 0.0f;
#pragma unroll
            for (int dy = 0; dy < KHW; ++dy) {
                const float* rowp = Bc + dy * WCOLS + cbase;
                float2 s01 = *(const float2*)(rowp);
                float2 s23 = *(const float2*)(rowp + 2);
                float2 s45 = *(const float2*)(rowp + 4);
                float s0 = s01.x, s1 = s01.y, s2 = s23.x,
                      s3 = s23.y, s4 = s45.x, s5 = s45.y;
                a0e = fmaf(gm0[dy*5+0], s0, a0e);  a1e = fmaf(gm1[dy*5+0], s1, a1e);
                a0o = fmaf(gm0[dy*5+1], s1, a0o);  a1o = fmaf(gm1[dy*5+1], s2, a1o);
                a0e = fmaf(gm0[dy*5+2], s2, a0e);  a1e = fmaf(gm1[dy*5+2], s3, a1e);
                a0o = fmaf(gm0[dy*5+3], s3, a0o);  a1o = fmaf(gm1[dy*5+3], s4, a1o);
                a0e = fmaf(gm0[dy*5+4], s4, a0e);  a1e = fmaf(gm1[dy*5+4], s5, a1e);
            }
            *(float2*)(outp + (size_t)(g * CHG + ch) * PLANE) =
                make_float2(a0e + a0o, a1e + a1o);
        }

        s_rd = (s_rd == NSTAGE - 1) ? 0 : s_rd + 1;
        s_wr = (s_wr == NSTAGE - 1) ? 0 : s_wr + 1;
    }
}

extern "C" void kernel_launch(void* const* d_in, const int* in_sizes, int n_in,
                              void* d_out, int out_size)
{
    const float* xyz     = (const float*)d_in[0];
    const float* softmax = (const float*)d_in[1];
    const void*  mask    = d_in[2];
    float*       out     = (float*)d_out;

    dim3 grid(WWID / TILE, HH, NN);   // (8, 64, 4) = 2048 blocks
    dim3 block(TPB);
    lcxyz_kernel<<<grid, block>>>(xyz, softmax, mask, out);
}

// round 11
// speedup vs baseline: 1.5921x; 1.0351x over previous
#include <cuda_runtime.h>

#define NN    4
#define CC    20
#define HH    64
#define WWID  2048
#define KHW   5
#define PLANE (HH * WWID)     // 131072

#define TPB   128
#define TILE  256             // output px per block, 2 px/thread
#define COLS  264             // staged cols: ww = w0-4 .. w0+259
#define NV4   (COLS / 4)      // 66 float4 per row
#define CH_PER_G   2
#define NGROUPS    (CC / CH_PER_G)           // 10
#define STAGE_FLTS (CH_PER_G * KHW * COLS)   // 2640 floats per ring stage
#define NSTAGE     4                          // 42240 B total
#define SLOTS      (CH_PER_G * KHW * NV4)    // 660 float4 copies per group
#define SLOTS_FULL 5                          // 128*5 = 640
#define SLOTS_REM  (SLOTS - TPB * SLOTS_FULL) // 20 (threads 0..19)

typedef unsigned long long u64;

__device__ __forceinline__ void cp_async16(void* smem, const void* gmem)
{
    unsigned saddr = (unsigned)__cvta_generic_to_shared(smem);
    asm volatile("cp.async.cg.shared.global [%0], [%1], 16;\n"
                 :: "r"(saddr), "l"(gmem));
}
__device__ __forceinline__ void cp_commit()
{
    asm volatile("cp.async.commit_group;\n" ::: "memory");
}
template <int N>
__device__ __forceinline__ void cp_wait()
{
    asm volatile("cp.async.wait_group %0;\n" :: "n"(N) : "memory");
}

__device__ __forceinline__ u64 pk(float lo, float hi)
{
    u64 r; asm("mov.b64 %0, {%1, %2};" : "=l"(r) : "f"(lo), "f"(hi)); return r;
}
__device__ __forceinline__ void upk(u64 v, float& lo, float& hi)
{
    asm("mov.b64 {%0, %1}, %2;" : "=f"(lo), "=f"(hi) : "l"(v));
}
__device__ __forceinline__ u64 ffma2(u64 a, u64 b, u64 c)   // a*b + c (packed f32x2)
{
    u64 d; asm("fma.rn.f32x2 %0, %1, %2, %3;" : "=l"(d) : "l"(a), "l"(b), "l"(c));
    return d;
}

__global__ __launch_bounds__(TPB, 5)
void lcxyz_kernel(const float* __restrict__ xyz,
                  const float* __restrict__ softmax,
                  const void* __restrict__ mask,
                  float* __restrict__ out)
{
    __shared__ float ring[NSTAGE * STAGE_FLTS];
    __shared__ int   sh_mode;

    const int t  = threadIdx.x;
    const int w0 = blockIdx.x * TILE;
    const int h  = blockIdx.y;
    const int n  = blockIdx.z;

    // ---- mask dtype detection (warp 0): 0=u8, 1=i32, 2=f32 ----
    if (t < 32) {
        const unsigned* m = (const unsigned*)mask;
        unsigned w1 = m[t], w2 = m[t + 32];
        bool i32ok = (w1 <= 1u) && (w2 <= 1u);
        bool f32ok = (w1 == 0u || w1 == 0x3F800000u) &&
                     (w2 == 0u || w2 == 0x3F800000u);
        unsigned bi = __ballot_sync(0xFFFFFFFFu, i32ok);
        unsigned bf = __ballot_sync(0xFFFFFFFFu, f32ok);
        if (t == 0) sh_mode = (bi == 0xFFFFFFFFu) ? 1 : ((bf == 0xFFFFFFFFu) ? 2 : 0);
    }

    int hrow[KHW];
#pragma unroll
    for (int r = 0; r < KHW; ++r)
        hrow[r] = min(max(h + r - 2, 0), HH - 1);

    const float* sm_base = softmax + (size_t)(n * CC) * PLANE;

    // ---- Precompute staging slots: 5 per thread + 1 extra for t<20 ----
    unsigned soff[SLOTS_FULL], goff[SLOTS_FULL];
    unsigned soffX = 0, goffX = 0;
    const bool hasX = (t < SLOTS_REM);
#pragma unroll
    for (int k = 0; k <= SLOTS_FULL; ++k) {
        int j = (k < SLOTS_FULL) ? (t + TPB * k) : (TPB * SLOTS_FULL + t);
        int ch  = j / (KHW * NV4);
        int rem = j - ch * (KHW * NV4);
        int rr  = rem / NV4;
        int i   = rem - rr * NV4;
        unsigned so = ch * (KHW * COLS) + rr * COLS + 4 * i;
        int gidx = hrow[rr] * WWID + (w0 - 4) + 4 * i;
        gidx = min(max(gidx, 0), PLANE - 4);     // edge garbage killed by weight 0
        unsigned go = ch * PLANE + gidx;
        if (k < SLOTS_FULL) { soff[k] = so; goff[k] = go; }
        else                { soffX   = so; goffX   = go; }
    }

    // ---- Prologue: prefetch groups 0 (stage 0) and 1 (stage 1) ----
#pragma unroll
    for (int k = 0; k < SLOTS_FULL; ++k)
        cp_async16(ring + soff[k], sm_base + goff[k]);
    if (hasX) cp_async16(ring + soffX, sm_base + goffX);
    cp_commit();
#pragma unroll
    for (int k = 0; k < SLOTS_FULL; ++k)
        cp_async16(ring + STAGE_FLTS + soff[k], sm_base + CH_PER_G * PLANE + goff[k]);
    if (hasX) cp_async16(ring + STAGE_FLTS + soffX, sm_base + CH_PER_G * PLANE + goffX);
    cp_commit();

    __syncthreads();    // sh_mode visible
    const int mmode = sh_mode;

    // ---- Phase 1: masked Gaussian weights, packed f32x2 layout ----
    const int wa = w0 + 2 * t;
    const int cc = 2 * t + 4;

    const float* Xx = xyz + (size_t)n * 3 * PLANE;
    const float* Xy = Xx + PLANE;
    const float* Xz = Xy + PLANE;
    const size_t mbase = (size_t)n * PLANE;
    const unsigned char* mk_u8  = (const unsigned char*)mask + mbase;
    const int*           mk_i32 = (const int*)mask + mbase;
    const float*         mk_f32 = (const float*)mask + mbase;

    const float cx0 = Xx[h * WWID + wa],     cy0 = Xy[h * WWID + wa],     cz0 = Xz[h * WWID + wa];
    const float cx1 = Xx[h * WWID + wa + 1], cy1 = Xy[h * WWID + wa + 1], cz1 = Xz[h * WWID + wa + 1];

    // Zero-padded length-6 kernels over window s0..s5, packed in aligned pairs:
    //   out0: W0=(g0_0,g0_1)  W1=(g0_2,g0_3)  W2=(g0_4, 0  )
    //   out1: V0=( 0 ,g1_0)   V1=(g1_1,g1_2)  V2=(g1_3,g1_4)
    u64 W0[KHW], W1[KHW], W2[KHW], V0[KHW], V1[KHW], V2[KHW];
#pragma unroll
    for (int dy = 0; dy < KHW; ++dy) {
        const int hc  = hrow[dy];
        const int hh  = h + dy - 2;
        const bool hok = (hh >= 0) && (hh < HH);
        float m[6], nx[6], ny[6], nz[6];
#pragma unroll
        for (int j = 0; j < 6; ++j) {
            int wraw = wa + j - 2;
            int ww = min(max(wraw, 0), WWID - 1);
            int idx = hc * WWID + ww;
            nx[j] = Xx[idx];  ny[j] = Xy[idx];  nz[j] = Xz[idx];
            bool ok = hok && (wraw >= 0) && (wraw < WWID);
            float mv = 0.0f;
            if (ok) {
                if (mmode == 1)      mv = (float)mk_i32[idx];
                else if (mmode == 2) mv = mk_f32[idx];
                else                 mv = (float)mk_u8[idx];
            }
            m[j] = mv;
        }
        float g0[KHW], g1[KHW];
#pragma unroll
        for (int dx = 0; dx < KHW; ++dx) {
            float ax = nx[dx] - cx0, ay = ny[dx] - cy0, az = nz[dx] - cz0;
            float d2a = fmaf(ax, ax, fmaf(ay, ay, az * az));
            g0[dx] = m[dx] * __expf(-0.5f * d2a);
            float bx = nx[dx+1] - cx1, by = ny[dx+1] - cy1, bz = nz[dx+1] - cz1;
            float d2b = fmaf(bx, bx, fmaf(by, by, bz * bz));
            g1[dx] = m[dx+1] * __expf(-0.5f * d2b);
        }
        W0[dy] = pk(g0[0], g0[1]);
        W1[dy] = pk(g0[2], g0[3]);
        W2[dy] = pk(g0[4], 0.0f);
        V0[dy] = pk(0.0f,  g1[0]);
        V1[dy] = pk(g1[1], g1[2]);
        V2[dy] = pk(g1[3], g1[4]);
    }

    // ---- Phase 2: 10 groups, 4-stage ring, prefetch distance 2 ----
    float* outp = out + ((size_t)(n * CC) * HH + h) * WWID + wa;

    for (int g = 0; g < NGROUPS; ++g) {
        if (g + 2 < NGROUPS) {
            const float* gb = sm_base + (size_t)(g + 2) * (CH_PER_G * PLANE);
            float* buf = ring + ((g + 2) & (NSTAGE - 1)) * STAGE_FLTS;
#pragma unroll
            for (int k = 0; k < SLOTS_FULL; ++k)
                cp_async16(buf + soff[k], gb + goff[k]);
            if (hasX) cp_async16(buf + soffX, gb + goffX);
            cp_commit();
            cp_wait<2>();       // group g complete; g+1, g+2 may be in flight
        } else if (g + 1 < NGROUPS) {
            cp_wait<1>();
        } else {
            cp_wait<0>();
        }
        __syncthreads();        // data visible; also fences stage reuse

        const float* B = ring + (g & (NSTAGE - 1)) * STAGE_FLTS;
#pragma unroll
        for (int ch = 0; ch < CH_PER_G; ++ch) {
            const float* Bc = B + ch * (KHW * COLS) + (cc - 2);   // window start (8B aligned)
            u64 Q0 = 0, Q1 = 0;     // packed (0.0f, 0.0f)
#pragma unroll
            for (int dy = 0; dy < KHW; ++dy) {
                const u64* rp = (const u64*)(Bc + dy * COLS);
                u64 s01 = rp[0], s23 = rp[1], s45 = rp[2];
                Q0 = ffma2(W0[dy], s01, Q0);
                Q1 = ffma2(V0[dy], s01, Q1);
                Q0 = ffma2(W1[dy], s23, Q0);
                Q1 = ffma2(V1[dy], s23, Q1);
                Q0 = ffma2(W2[dy], s45, Q0);
                Q1 = ffma2(V2[dy], s45, Q1);
            }
            float q0l, q0h, q1l, q1h;
            upk(Q0, q0l, q0h);
            upk(Q1, q1l, q1h);
            *(float2*)(outp + (size_t)(g * CH_PER_G + ch) * PLANE) =
                make_float2(q0l + q0h, q1l + q1h);
        }
        // single barrier per group: stage (g+2)%4 written above was last read
        // at iter g-2; the iter g-1 and iter g barriers separate read from write.
    }
}

extern "C" void kernel_launch(void* const* d_in, const int* in_sizes, int n_in,
                              void* d_out, int out_size)
{
    const float* xyz     = (const float*)d_in[0];
    const float* softmax = (const float*)d_in[1];
    const void*  mask    = d_in[2];
    float*       out     = (float*)d_out;

    dim3 grid(WWID / TILE, HH, NN);   // (8, 64, 4) = 2048 blocks
    dim3 block(TPB);
    lcxyz_kernel<<<grid, block>>>(xyz, softmax, mask, out);
}